// round 11
// baseline (speedup 1.0000x reference)
#include <cuda_runtime.h>
#include <cuda_fp16.h>
#include <cstdint>

#define T_SEQ 128
#define E_DIM 256
#define H_DIM 64

// ---- SMEM byte layout ----
#define SQ_B   0u          // Q [128][72]h
#define SK_B   18432u      // K [128][72]h
#define SV_B   36864u      // V [128][72]h  (row=token, col=h)
#define SW_B   55296u      // W resident [4 ec][192][72]h = 110592 B
#define SP_B   55296u      // P [128][136]h  (overlays W after phase 1)
#define PM_B   165888u     // float[4][128] partial row max
#define PS_B   167936u     // float[4][128] partial row sum
#define SMEM_BYTES 169984u

#define LDA 144            // 72 halves per row (bytes)
#define LDPB 272           // 136 halves per row (bytes)
#define W_EC_STRIDE 27648u // 192*72*2 bytes per E-chunk

// log2(e)/8  (softmax in log2 domain)
#define SCL 0.18033688f

// W pre-converted fp16, pre-transposed: [ec(4)][n(192)=Wq|Wk|Wv rows][k(72)]
__device__ __align__(16) __half g_wt[4 * 192 * 72];

// ---------------- helpers ----------------
__device__ __forceinline__ uint32_t smem_u32(const void* p) {
    uint32_t a;
    asm("{ .reg .u64 t; cvta.to.shared.u64 t, %1; cvt.u32.u64 %0, t; }" : "=r"(a) : "l"(p));
    return a;
}
__device__ __forceinline__ uint32_t pack2(float lo, float hi) {
    uint32_t r;
    asm("cvt.rn.f16x2.f32 %0, %1, %2;" : "=r"(r) : "f"(hi), "f"(lo));  // first src -> high
    return r;
}
__device__ __forceinline__ float fex2(float x) {
    float r;
    asm("ex2.approx.f32 %0, %1;" : "=f"(r) : "f"(x));
    return r;
}
#define LDSM_X4(R, a) \
    asm volatile("ldmatrix.sync.aligned.m8n8.x4.shared.b16 {%0,%1,%2,%3}, [%4];" \
        : "=r"((R)[0]), "=r"((R)[1]), "=r"((R)[2]), "=r"((R)[3]) : "r"(a))
#define LDSM_X4T(R, a) \
    asm volatile("ldmatrix.sync.aligned.m8n8.x4.trans.shared.b16 {%0,%1,%2,%3}, [%4];" \
        : "=r"((R)[0]), "=r"((R)[1]), "=r"((R)[2]), "=r"((R)[3]) : "r"(a))
#define MMA16816(D, A, B0, B1) \
    asm volatile("mma.sync.aligned.m16n8k16.row.col.f32.f16.f16.f32 " \
        "{%0,%1,%2,%3}, {%4,%5,%6,%7}, {%8,%9}, {%0,%1,%2,%3};" \
        : "+f"((D)[0]), "+f"((D)[1]), "+f"((D)[2]), "+f"((D)[3]) \
        : "r"((A)[0]), "r"((A)[1]), "r"((A)[2]), "r"((A)[3]), "r"(B0), "r"(B1))
#define CP_ASYNC16(dst, src) \
    asm volatile("cp.async.cg.shared.global [%0], [%1], 16;" :: "r"(dst), "l"(src))
#define CP_COMMIT()  asm volatile("cp.async.commit_group;" ::: "memory")
#define CP_WAIT0()   asm volatile("cp.async.wait_group 0;" ::: "memory")

// load A fragments (2 m-tiles) for global k16-step `k` straight from gmem (fp32 -> fp16)
#define LOAD_A(dst, k) do {                                                   \
    const int kb_ = (k) * 16;                                                 \
    _Pragma("unroll")                                                         \
    for (int mt_ = 0; mt_ < 2; mt_++) {                                       \
        const float* base_ = xw + mt_ * 16 * E_DIM + kb_;                     \
        float2 f0_ = *reinterpret_cast<const float2*>(base_);                 \
        float2 f1_ = *reinterpret_cast<const float2*>(base_ + 8 * E_DIM);     \
        float2 f2_ = *reinterpret_cast<const float2*>(base_ + 8);             \
        float2 f3_ = *reinterpret_cast<const float2*>(base_ + 8 * E_DIM + 8); \
        (dst)[mt_][0] = pack2(f0_.x, f0_.y);                                  \
        (dst)[mt_][1] = pack2(f1_.x, f1_.y);                                  \
        (dst)[mt_][2] = pack2(f2_.x, f2_.y);                                  \
        (dst)[mt_][3] = pack2(f3_.x, f3_.y);                                  \
    }                                                                         \
} while (0)

// ---------------- W prep: fp32 [E][H] -> fp16 tiles [ec][n][72] ----------------
__global__ void prep_w_kernel(const float* __restrict__ Wq,
                              const float* __restrict__ Wk,
                              const float* __restrict__ Wv) {
    int blk = blockIdx.x;             // ec*3 + m
    int ec = blk / 3, m = blk % 3;
    const float* W = (m == 0) ? Wq : (m == 1) ? Wk : Wv;
#pragma unroll
    for (int i = 0; i < 16; i++) {
        int e = threadIdx.x + i * 256;      // 0..4095
        int h = e >> 6, k = e & 63;
        g_wt[((size_t)ec * 192 + m * 64 + h) * 72 + k] =
            __float2half_rn(W[(ec * 64 + k) * H_DIM + h]);
    }
}

// ---------------- main kernel: 512 threads, 16 warps ----------------
__global__ __launch_bounds__(512, 1)
void attn_fp16_kernel(const float* __restrict__ x, float* __restrict__ out) {
    extern __shared__ char smem[];
    const uint32_t sbase = smem_u32(smem);
    const int tid = threadIdx.x, warp = tid >> 5, lane = tid & 31;
    const int g = lane >> 2, t = lane & 3;
    const int wm = warp & 3, wn = warp >> 2;     // 4 x 4 warp grid
    const int m0 = wm * 32;
    const size_t b = blockIdx.x;
    const float* xb = x + b * (size_t)(T_SEQ * E_DIM);

    // =============== Phase 1: QKV = x @ Wt ===============
    // W: one-shot cp.async into resident SMEM. x: A-fragments direct gmem->regs.
    {
        const char* wsrc = reinterpret_cast<const char*>(g_wt);
#pragma unroll
        for (int i = 0; i < 14; i++) {
            int idx = tid + i * 512;
            if (idx < 6912) CP_ASYNC16(sbase + SW_B + idx * 16, wsrc + idx * 16);
        }
        CP_COMMIT();
    }

    float acc1[2][6][4];
#pragma unroll
    for (int i = 0; i < 2; i++)
#pragma unroll
        for (int j = 0; j < 6; j++)
#pragma unroll
            for (int r = 0; r < 4; r++) acc1[i][j][r] = 0.f;

    const int n01 = wn * 48;
    const float* xw = xb + (size_t)(m0 + g) * E_DIM + t * 2;

    uint32_t a[2][2][4], bf[2][3][4];
    LOAD_A(a[0], 0);     // gmem loads, independent of SMEM — issue before barrier

    CP_WAIT0();
    __syncthreads();     // W resident

    const uint32_t bbase = sbase + SW_B
                         + (n01 + ((lane >> 4) << 3) + (lane & 7)) * LDA
                         + ((lane >> 3) & 1) * 16;
#pragma unroll
    for (int bt = 0; bt < 3; bt++) LDSM_X4(bf[0][bt], bbase + bt * 16 * LDA);

#pragma unroll
    for (int k = 0; k < 16; k++) {           // global k16 steps over E=256
        const int cur = k & 1, nxt = cur ^ 1;
        if (k < 15) {
            LOAD_A(a[nxt], k + 1);
            const uint32_t bk = bbase + ((k + 1) >> 2) * W_EC_STRIDE + ((k + 1) & 3) * 32;
#pragma unroll
            for (int bt = 0; bt < 3; bt++) LDSM_X4(bf[nxt][bt], bk + bt * 16 * LDA);
        }
#pragma unroll
        for (int mt = 0; mt < 2; mt++)
#pragma unroll
            for (int nt = 0; nt < 6; nt++)
                MMA16816(acc1[mt][nt], a[cur][mt], bf[cur][nt >> 1][(nt & 1) * 2],
                         bf[cur][nt >> 1][(nt & 1) * 2 + 1]);
    }

    // epilogue 1: acc -> fp16 Q/K/V tiles
#pragma unroll
    for (int mt = 0; mt < 2; mt++) {
        int rlo = m0 + mt * 16 + g, rhi = rlo + 8;
#pragma unroll
        for (int nt = 0; nt < 6; nt++) {
            int cg = n01 + nt * 8 + t * 2;
            int sel = cg >> 6, cl = cg & 63;
            uint32_t base = (sel == 0) ? SQ_B : (sel == 1) ? SK_B : SV_B;
            *reinterpret_cast<uint32_t*>(smem + base + rlo * LDA + cl * 2) =
                pack2(acc1[mt][nt][0], acc1[mt][nt][1]);
            *reinterpret_cast<uint32_t*>(smem + base + rhi * LDA + cl * 2) =
                pack2(acc1[mt][nt][2], acc1[mt][nt][3]);
        }
    }
    __syncthreads();

    // =============== Phase 2a: S = Q @ K^T, causal softmax -> P ===============
    const int n02 = wn * 32;
    const bool active = (n02 <= m0 + 31);     // wn <= wm
    float acc2[2][4][4];
    float* pm = reinterpret_cast<float*>(smem + PM_B);
    float* ps = reinterpret_cast<float*>(smem + PS_B);
    float fscale[2][2];   // per (mt, lo/hi) local max stash (log2 domain)

    if (active) {
#pragma unroll
        for (int i = 0; i < 2; i++)
#pragma unroll
            for (int j = 0; j < 4; j++)
#pragma unroll
                for (int r = 0; r < 4; r++) acc2[i][j][r] = 0.f;

        const uint32_t arow = sbase + SQ_B + (m0 + (lane & 15)) * LDA + (lane >> 4) * 16;
        const uint32_t brow = sbase + SK_B + (n02 + ((lane >> 4) << 3) + (lane & 7)) * LDA
                                          + ((lane >> 3) & 1) * 16;
        uint32_t aq[2][2][4], bk2[2][2][4];
#pragma unroll
        for (int mt = 0; mt < 2; mt++) LDSM_X4(aq[0][mt], arow + mt * 16 * LDA);
#pragma unroll
        for (int bt = 0; bt < 2; bt++) LDSM_X4(bk2[0][bt], brow + bt * 16 * LDA);

#pragma unroll
        for (int kt = 0; kt < 4; kt++) {
            const int cur = kt & 1, nxt = cur ^ 1;
            if (kt < 3) {
#pragma unroll
                for (int mt = 0; mt < 2; mt++)
                    LDSM_X4(aq[nxt][mt], arow + mt * 16 * LDA + (kt + 1) * 32);
#pragma unroll
                for (int bt = 0; bt < 2; bt++)
                    LDSM_X4(bk2[nxt][bt], brow + bt * 16 * LDA + (kt + 1) * 32);
            }
#pragma unroll
            for (int mt = 0; mt < 2; mt++)
#pragma unroll
                for (int nt = 0; nt < 4; nt++)
                    MMA16816(acc2[mt][nt], aq[cur][mt], bk2[cur][nt >> 1][(nt & 1) * 2],
                             bk2[cur][nt >> 1][(nt & 1) * 2 + 1]);
        }

        // mask + local (32-col chunk) softmax partials (log2 domain)
#pragma unroll
        for (int mt = 0; mt < 2; mt++) {
            int rlo = m0 + mt * 16 + g, rhi = rlo + 8;
            float mlo = -1e30f, mhi = -1e30f;
#pragma unroll
            for (int nt = 0; nt < 4; nt++)
#pragma unroll
                for (int j = 0; j < 2; j++) {
                    int c = n02 + nt * 8 + t * 2 + j;
                    float v0 = acc2[mt][nt][j] * SCL;
                    v0 = (c <= rlo) ? v0 : -1e30f;
                    acc2[mt][nt][j] = v0; mlo = fmaxf(mlo, v0);
                    float v1 = acc2[mt][nt][2 + j] * SCL;
                    v1 = (c <= rhi) ? v1 : -1e30f;
                    acc2[mt][nt][2 + j] = v1; mhi = fmaxf(mhi, v1);
                }
            mlo = fmaxf(mlo, __shfl_xor_sync(0xffffffffu, mlo, 1));
            mlo = fmaxf(mlo, __shfl_xor_sync(0xffffffffu, mlo, 2));
            mhi = fmaxf(mhi, __shfl_xor_sync(0xffffffffu, mhi, 1));
            mhi = fmaxf(mhi, __shfl_xor_sync(0xffffffffu, mhi, 2));
            float slo = 0.f, shi = 0.f;
#pragma unroll
            for (int nt = 0; nt < 4; nt++)
#pragma unroll
                for (int j = 0; j < 2; j++) {
                    float e0 = fex2(acc2[mt][nt][j] - mlo);
                    float e1 = fex2(acc2[mt][nt][2 + j] - mhi);
                    acc2[mt][nt][j] = e0;  acc2[mt][nt][2 + j] = e1;
                    slo += e0; shi += e1;
                }
            slo += __shfl_xor_sync(0xffffffffu, slo, 1);
            slo += __shfl_xor_sync(0xffffffffu, slo, 2);
            shi += __shfl_xor_sync(0xffffffffu, shi, 1);
            shi += __shfl_xor_sync(0xffffffffu, shi, 2);
            if (t == 0) {
                pm[wn * 128 + rlo] = mlo;  pm[wn * 128 + rhi] = mhi;
                ps[wn * 128 + rlo] = slo;  ps[wn * 128 + rhi] = shi;
            }
            fscale[mt][0] = mlo;  fscale[mt][1] = mhi;
        }
    } else {
        // fully masked tile: contribute empty partials
        if (t == 0) {
#pragma unroll
            for (int mt = 0; mt < 2; mt++) {
                int rlo = m0 + mt * 16 + g, rhi = rlo + 8;
                pm[wn * 128 + rlo] = -1e30f;  pm[wn * 128 + rhi] = -1e30f;
                ps[wn * 128 + rlo] = 0.f;     ps[wn * 128 + rhi] = 0.f;
            }
        }
    }
    __syncthreads();

    // combine partials, write P (fp16). Inactive warps' P tiles are never read
    // by the causally-skipped PV loop, so they write nothing.
    if (active) {
#pragma unroll
        for (int mt = 0; mt < 2; mt++) {
            int rlo = m0 + mt * 16 + g, rhi = rlo + 8;
            float M0 = pm[rlo], M1 = pm[128 + rlo], M2 = pm[256 + rlo], M3 = pm[384 + rlo];
            float Mlo = fmaxf(fmaxf(M0, M1), fmaxf(M2, M3));
            float Zlo = ps[rlo] * fex2(M0 - Mlo) + ps[128 + rlo] * fex2(M1 - Mlo)
                      + ps[256 + rlo] * fex2(M2 - Mlo) + ps[384 + rlo] * fex2(M3 - Mlo);
            float N0 = pm[rhi], N1 = pm[128 + rhi], N2 = pm[256 + rhi], N3 = pm[384 + rhi];
            float Mhi = fmaxf(fmaxf(N0, N1), fmaxf(N2, N3));
            float Zhi = ps[rhi] * fex2(N0 - Mhi) + ps[128 + rhi] * fex2(N1 - Mhi)
                      + ps[256 + rhi] * fex2(N2 - Mhi) + ps[384 + rhi] * fex2(N3 - Mhi);
            float flo = fex2(fscale[mt][0] - Mlo) / Zlo;
            float fhi = fex2(fscale[mt][1] - Mhi) / Zhi;
#pragma unroll
            for (int nt = 0; nt < 4; nt++) {
                int c = n02 + nt * 8 + t * 2;
                *reinterpret_cast<uint32_t*>(smem + SP_B + rlo * LDPB + c * 2) =
                    pack2(acc2[mt][nt][0] * flo, acc2[mt][nt][1] * flo);
                *reinterpret_cast<uint32_t*>(smem + SP_B + rhi * LDPB + c * 2) =
                    pack2(acc2[mt][nt][2] * fhi, acc2[mt][nt][3] * fhi);
            }
        }
    }
    __syncthreads();

    // =============== Phase 2c: O = P @ V  (causal kt-skip) ===============
    const int n03 = wn * 16;
    float acc3[2][2][4];
#pragma unroll
    for (int i = 0; i < 2; i++)
#pragma unroll
        for (int j = 0; j < 2; j++)
#pragma unroll
            for (int r = 0; r < 4; r++) acc3[i][j][r] = 0.f;

    const uint32_t prow = sbase + SP_B + (m0 + (lane & 15)) * LDPB + (lane >> 4) * 16;
    const uint32_t vbase = sbase + SV_B
                         + (((lane >> 3) & 1) * 8 + (lane & 7)) * LDA
                         + (lane >> 4) * 16 + n03 * 2;
    const int ktend = 2 * wm + 2;     // P cols beyond m0+31 are exactly zero
#pragma unroll 2
    for (int kt = 0; kt < ktend; kt++) {
        uint32_t a3[2][4], bv[4];
#pragma unroll
        for (int mt = 0; mt < 2; mt++) LDSM_X4(a3[mt], prow + mt * 16 * LDPB + kt * 32);
        LDSM_X4T(bv, vbase + kt * 16 * LDA);
#pragma unroll
        for (int mt = 0; mt < 2; mt++) {
            MMA16816(acc3[mt][0], a3[mt], bv[0], bv[1]);
            MMA16816(acc3[mt][1], a3[mt], bv[2], bv[3]);
        }
    }

    // output: fp32 float2 stores
    float* ob = out + b * (size_t)(T_SEQ * H_DIM);
#pragma unroll
    for (int mt = 0; mt < 2; mt++) {
        int rlo = m0 + mt * 16 + g, rhi = rlo + 8;
#pragma unroll
        for (int nt = 0; nt < 2; nt++) {
            int c = n03 + nt * 8 + t * 2;
            *reinterpret_cast<float2*>(ob + rlo * H_DIM + c) =
                make_float2(acc3[mt][nt][0], acc3[mt][nt][1]);
            *reinterpret_cast<float2*>(ob + rhi * H_DIM + c) =
                make_float2(acc3[mt][nt][2], acc3[mt][nt][3]);
        }
    }
}

extern "C" void kernel_launch(void* const* d_in, const int* in_sizes, int n_in,
                              void* d_out, int out_size) {
    const float* x  = (const float*)d_in[0];
    const float* Wq = (const float*)d_in[1];
    const float* Wk = (const float*)d_in[2];
    const float* Wv = (const float*)d_in[3];
    float* out = (float*)d_out;

    int B = in_sizes[0] / (T_SEQ * E_DIM);   // 4096

    cudaFuncSetAttribute(attn_fp16_kernel,
                         cudaFuncAttributeMaxDynamicSharedMemorySize,
                         (int)SMEM_BYTES);

    prep_w_kernel<<<12, 256>>>(Wq, Wk, Wv);
    attn_fp16_kernel<<<B, 512, SMEM_BYTES>>>(x, out);
}

// round 12
// speedup vs baseline: 1.5868x; 1.5868x over previous
#include <cuda_runtime.h>
#include <cuda_fp16.h>
#include <cstdint>

#define T_SEQ 128
#define E_DIM 256
#define H_DIM 64

// ---- SMEM byte layout ----
#define SQ_B   0u          // Q [128][72]h
#define SK_B   18432u      // K [128][72]h
#define SV_B   36864u      // V [128][72]h  (row=token, col=h)
#define SX0_B  55296u      // x stage buf0 [128][72]h
#define SX1_B  73728u      // x stage buf1
#define SW0_B  92160u      // W stage buf0 [192][72]h
#define SW1_B  119808u     // W stage buf1
#define SP_B   55296u      // P [128][136]h (reuses x stages)
#define PM_B   147456u     // float[4][128] partial row max
#define PS_B   149504u     // float[4][128] partial row sum
#define SMEM_BYTES 151552u

#define LDA 144            // 72 halves per row
#define LDPB 272           // 136 halves per row

// log2(e)/8  (softmax in log2 domain; 1/sqrt(64) scale folded in)
#define SCL 0.18033688f

// W pre-converted fp16, pre-transposed: [ec(4)][n(192)=Wq|Wk|Wv rows][k(72)]
__device__ __align__(16) __half g_wt[4 * 192 * 72];

// ---------------- helpers ----------------
__device__ __forceinline__ uint32_t smem_u32(const void* p) {
    uint32_t a;
    asm("{ .reg .u64 t; cvta.to.shared.u64 t, %1; cvt.u32.u64 %0, t; }" : "=r"(a) : "l"(p));
    return a;
}
__device__ __forceinline__ uint32_t pack2(float lo, float hi) {
    uint32_t r;
    asm("cvt.rn.f16x2.f32 %0, %1, %2;" : "=r"(r) : "f"(hi), "f"(lo));  // first src -> high
    return r;
}
__device__ __forceinline__ float fex2(float x) {
    float r;
    asm("ex2.approx.f32 %0, %1;" : "=f"(r) : "f"(x));
    return r;
}
#define LDSM_X4(R, a) \
    asm volatile("ldmatrix.sync.aligned.m8n8.x4.shared.b16 {%0,%1,%2,%3}, [%4];" \
        : "=r"((R)[0]), "=r"((R)[1]), "=r"((R)[2]), "=r"((R)[3]) : "r"(a))
#define LDSM_X4T(R, a) \
    asm volatile("ldmatrix.sync.aligned.m8n8.x4.trans.shared.b16 {%0,%1,%2,%3}, [%4];" \
        : "=r"((R)[0]), "=r"((R)[1]), "=r"((R)[2]), "=r"((R)[3]) : "r"(a))
#define MMA16816(D, A, B0, B1) \
    asm volatile("mma.sync.aligned.m16n8k16.row.col.f32.f16.f16.f32 " \
        "{%0,%1,%2,%3}, {%4,%5,%6,%7}, {%8,%9}, {%0,%1,%2,%3};" \
        : "+f"((D)[0]), "+f"((D)[1]), "+f"((D)[2]), "+f"((D)[3]) \
        : "r"((A)[0]), "r"((A)[1]), "r"((A)[2]), "r"((A)[3]), "r"(B0), "r"(B1))
#define CP_ASYNC16(dst, src) \
    asm volatile("cp.async.cg.shared.global [%0], [%1], 16;" :: "r"(dst), "l"(src))
#define CP_COMMIT()  asm volatile("cp.async.commit_group;" ::: "memory")
#define CP_WAIT0()   asm volatile("cp.async.wait_group 0;" ::: "memory")

// ---------------- W prep: fp32 [E][H] -> fp16 tiles [ec][n][72] ----------------
__global__ void prep_w_kernel(const float* __restrict__ Wq,
                              const float* __restrict__ Wk,
                              const float* __restrict__ Wv) {
    int blk = blockIdx.x;             // ec*3 + m
    int ec = blk / 3, m = blk % 3;
    const float* W = (m == 0) ? Wq : (m == 1) ? Wk : Wv;
#pragma unroll
    for (int i = 0; i < 16; i++) {
        int e = threadIdx.x + i * 256;      // 0..4095
        int h = e >> 6, k = e & 63;
        g_wt[((size_t)ec * 192 + m * 64 + h) * 72 + k] =
            __float2half_rn(W[(ec * 64 + k) * H_DIM + h]);
    }
}

// ---------------- main kernel: 512 threads, 16 warps ----------------
__global__ __launch_bounds__(512, 1)
void attn_fp16_kernel(const float* __restrict__ x, float* __restrict__ out) {
    extern __shared__ char smem[];
    const uint32_t sbase = smem_u32(smem);
    const int tid = threadIdx.x, warp = tid >> 5, lane = tid & 31;
    const int g = lane >> 2, t = lane & 3;
    const int wm = warp & 3, wn = warp >> 2;     // 4 x 4 warp grid
    const int m0 = wm * 32;
    const size_t b = blockIdx.x;
    const float* xb = x + b * (size_t)(T_SEQ * E_DIM);

    // =============== Phase 1: QKV = x @ Wt  (E chunked x4, pipelined) ===============
    float acc1[2][6][4];
#pragma unroll
    for (int i = 0; i < 2; i++)
#pragma unroll
        for (int j = 0; j < 6; j++)
#pragma unroll
            for (int r = 0; r < 4; r++) acc1[i][j][r] = 0.f;

    const int n01 = wn * 48;
    float4 xr[4];

    // prologue: stage chunk 0
    {
#pragma unroll
        for (int i = 0; i < 2; i++) {
            int q = tid + i * 512, r = q >> 3, c8 = q & 7;
            const float* p = xb + r * E_DIM + c8 * 8;
            xr[2 * i]     = *reinterpret_cast<const float4*>(p);
            xr[2 * i + 1] = *reinterpret_cast<const float4*>(p + 4);
        }
        const char* wsrc = reinterpret_cast<const char*>(g_wt);
#pragma unroll
        for (int i = 0; i < 4; i++) {
            int idx = tid + i * 512;
            if (idx < 1728) CP_ASYNC16(sbase + SW0_B + idx * 16, wsrc + idx * 16);
        }
        CP_COMMIT();
#pragma unroll
        for (int i = 0; i < 2; i++) {
            int q = tid + i * 512, r = q >> 3, c8 = q & 7;
            uint4 u;
            u.x = pack2(xr[2 * i].x,     xr[2 * i].y);
            u.y = pack2(xr[2 * i].z,     xr[2 * i].w);
            u.z = pack2(xr[2 * i + 1].x, xr[2 * i + 1].y);
            u.w = pack2(xr[2 * i + 1].z, xr[2 * i + 1].w);
            *reinterpret_cast<uint4*>(smem + SX0_B + r * LDA + c8 * 16) = u;
        }
        CP_WAIT0();
        __syncthreads();
    }

#pragma unroll
    for (int ec = 0; ec < 4; ec++) {
        const uint32_t sx = sbase + ((ec & 1) ? SX1_B : SX0_B);
        const uint32_t sw = sbase + ((ec & 1) ? SW1_B : SW0_B);
        const uint32_t sxn = sbase + ((ec & 1) ? SX0_B : SX1_B);
        const uint32_t swn = sbase + ((ec & 1) ? SW0_B : SW1_B);

        if (ec < 3) {   // prefetch next chunk: x -> regs, W -> cp.async
#pragma unroll
            for (int i = 0; i < 2; i++) {
                int q = tid + i * 512, r = q >> 3, c8 = q & 7;
                const float* p = xb + r * E_DIM + (ec + 1) * 64 + c8 * 8;
                xr[2 * i]     = *reinterpret_cast<const float4*>(p);
                xr[2 * i + 1] = *reinterpret_cast<const float4*>(p + 4);
            }
            const char* wsrc = reinterpret_cast<const char*>(g_wt) + (size_t)(ec + 1) * 27648;
#pragma unroll
            for (int i = 0; i < 4; i++) {
                int idx = tid + i * 512;
                if (idx < 1728) CP_ASYNC16(swn + idx * 16, wsrc + idx * 16);
            }
            CP_COMMIT();
        }

        // MMA over this chunk (K=64 -> 4 k16 steps)
        const uint32_t arow = sx + (m0 + (lane & 15)) * LDA + (lane >> 4) * 16;
        const uint32_t brow = sw + (n01 + ((lane >> 4) << 3) + (lane & 7)) * LDA
                                 + ((lane >> 3) & 1) * 16;
#pragma unroll
        for (int kt = 0; kt < 4; kt++) {
            uint32_t a[2][4], bf[3][4];
#pragma unroll
            for (int mt = 0; mt < 2; mt++) LDSM_X4(a[mt], arow + mt * 16 * LDA + kt * 32);
#pragma unroll
            for (int bt = 0; bt < 3; bt++) LDSM_X4(bf[bt], brow + bt * 16 * LDA + kt * 32);
#pragma unroll
            for (int mt = 0; mt < 2; mt++)
#pragma unroll
                for (int nt = 0; nt < 6; nt++)
                    MMA16816(acc1[mt][nt], a[mt], bf[nt >> 1][(nt & 1) * 2],
                             bf[nt >> 1][(nt & 1) * 2 + 1]);
        }

        if (ec < 3) {   // store prefetched x into the other buffer
#pragma unroll
            for (int i = 0; i < 2; i++) {
                int q = tid + i * 512, r = q >> 3, c8 = q & 7;
                uint4 u;
                u.x = pack2(xr[2 * i].x,     xr[2 * i].y);
                u.y = pack2(xr[2 * i].z,     xr[2 * i].w);
                u.z = pack2(xr[2 * i + 1].x, xr[2 * i + 1].y);
                u.w = pack2(xr[2 * i + 1].z, xr[2 * i + 1].w);
                *reinterpret_cast<uint4*>((char*)smem + (sxn - sbase) + r * LDA + c8 * 16) = u;
            }
        }
        CP_WAIT0();
        __syncthreads();
    }

    // epilogue 1: acc -> fp16 Q/K/V tiles
#pragma unroll
    for (int mt = 0; mt < 2; mt++) {
        int rlo = m0 + mt * 16 + g, rhi = rlo + 8;
#pragma unroll
        for (int nt = 0; nt < 6; nt++) {
            int cg = n01 + nt * 8 + t * 2;
            int sel = cg >> 6, cl = cg & 63;
            uint32_t base = (sel == 0) ? SQ_B : (sel == 1) ? SK_B : SV_B;
            *reinterpret_cast<uint32_t*>(smem + base + rlo * LDA + cl * 2) =
                pack2(acc1[mt][nt][0], acc1[mt][nt][1]);
            *reinterpret_cast<uint32_t*>(smem + base + rhi * LDA + cl * 2) =
                pack2(acc1[mt][nt][2], acc1[mt][nt][3]);
        }
    }
    __syncthreads();

    // =============== Phase 2a: S = Q @ K^T, causal softmax -> P ===============
    const int n02 = wn * 32;
    const bool active = (n02 <= m0 + 31);     // wn <= wm
    float acc2[2][4][4];
    float* pm = reinterpret_cast<float*>(smem + PM_B);
    float* ps = reinterpret_cast<float*>(smem + PS_B);
    float fscale[2][2];   // per (mt, lo/hi) local max stash (log2 domain)

    if (active) {
#pragma unroll
        for (int i = 0; i < 2; i++)
#pragma unroll
            for (int j = 0; j < 4; j++)
#pragma unroll
                for (int r = 0; r < 4; r++) acc2[i][j][r] = 0.f;

        const uint32_t arow = sbase + SQ_B + (m0 + (lane & 15)) * LDA + (lane >> 4) * 16;
        const uint32_t brow = sbase + SK_B + (n02 + ((lane >> 4) << 3) + (lane & 7)) * LDA
                                          + ((lane >> 3) & 1) * 16;
#pragma unroll
        for (int kt = 0; kt < 4; kt++) {
            uint32_t a[2][4], bf[2][4];
#pragma unroll
            for (int mt = 0; mt < 2; mt++) LDSM_X4(a[mt], arow + mt * 16 * LDA + kt * 32);
#pragma unroll
            for (int bt = 0; bt < 2; bt++) LDSM_X4(bf[bt], brow + bt * 16 * LDA + kt * 32);
#pragma unroll
            for (int mt = 0; mt < 2; mt++)
#pragma unroll
                for (int nt = 0; nt < 4; nt++)
                    MMA16816(acc2[mt][nt], a[mt], bf[nt >> 1][(nt & 1) * 2],
                             bf[nt >> 1][(nt & 1) * 2 + 1]);
        }

        // mask + local (32-col chunk) softmax partials (log2 domain)
#pragma unroll
        for (int mt = 0; mt < 2; mt++) {
            int rlo = m0 + mt * 16 + g, rhi = rlo + 8;
            float mlo = -1e30f, mhi = -1e30f;
#pragma unroll
            for (int nt = 0; nt < 4; nt++)
#pragma unroll
                for (int j = 0; j < 2; j++) {
                    int c = n02 + nt * 8 + t * 2 + j;
                    float v0 = acc2[mt][nt][j] * SCL;
                    v0 = (c <= rlo) ? v0 : -1e30f;
                    acc2[mt][nt][j] = v0; mlo = fmaxf(mlo, v0);
                    float v1 = acc2[mt][nt][2 + j] * SCL;
                    v1 = (c <= rhi) ? v1 : -1e30f;
                    acc2[mt][nt][2 + j] = v1; mhi = fmaxf(mhi, v1);
                }
            mlo = fmaxf(mlo, __shfl_xor_sync(0xffffffffu, mlo, 1));
            mlo = fmaxf(mlo, __shfl_xor_sync(0xffffffffu, mlo, 2));
            mhi = fmaxf(mhi, __shfl_xor_sync(0xffffffffu, mhi, 1));
            mhi = fmaxf(mhi, __shfl_xor_sync(0xffffffffu, mhi, 2));
            float slo = 0.f, shi = 0.f;
#pragma unroll
            for (int nt = 0; nt < 4; nt++)
#pragma unroll
                for (int j = 0; j < 2; j++) {
                    float e0 = fex2(acc2[mt][nt][j] - mlo);
                    float e1 = fex2(acc2[mt][nt][2 + j] - mhi);
                    acc2[mt][nt][j] = e0;  acc2[mt][nt][2 + j] = e1;
                    slo += e0; shi += e1;
                }
            slo += __shfl_xor_sync(0xffffffffu, slo, 1);
            slo += __shfl_xor_sync(0xffffffffu, slo, 2);
            shi += __shfl_xor_sync(0xffffffffu, shi, 1);
            shi += __shfl_xor_sync(0xffffffffu, shi, 2);
            if (t == 0) {
                pm[wn * 128 + rlo] = mlo;  pm[wn * 128 + rhi] = mhi;
                ps[wn * 128 + rlo] = slo;  ps[wn * 128 + rhi] = shi;
            }
            fscale[mt][0] = mlo;  fscale[mt][1] = mhi;
        }
    } else {
        // fully masked tile: contribute empty partials
        if (t == 0) {
#pragma unroll
            for (int mt = 0; mt < 2; mt++) {
                int rlo = m0 + mt * 16 + g, rhi = rlo + 8;
                pm[wn * 128 + rlo] = -1e30f;  pm[wn * 128 + rhi] = -1e30f;
                ps[wn * 128 + rlo] = 0.f;     ps[wn * 128 + rhi] = 0.f;
            }
        }
    }
    __syncthreads();

    // combine partials, write P (fp16). Inactive tiles (wn > wm) are never read
    // by the causally-skipped PV loop below, so they are not written at all.
    if (active) {
#pragma unroll
        for (int mt = 0; mt < 2; mt++) {
            int rlo = m0 + mt * 16 + g, rhi = rlo + 8;
            float M0 = pm[rlo], M1 = pm[128 + rlo], M2 = pm[256 + rlo], M3 = pm[384 + rlo];
            float Mlo = fmaxf(fmaxf(M0, M1), fmaxf(M2, M3));
            float Zlo = ps[rlo] * fex2(M0 - Mlo) + ps[128 + rlo] * fex2(M1 - Mlo)
                      + ps[256 + rlo] * fex2(M2 - Mlo) + ps[384 + rlo] * fex2(M3 - Mlo);
            float N0 = pm[rhi], N1 = pm[128 + rhi], N2 = pm[256 + rhi], N3 = pm[384 + rhi];
            float Mhi = fmaxf(fmaxf(N0, N1), fmaxf(N2, N3));
            float Zhi = ps[rhi] * fex2(N0 - Mhi) + ps[128 + rhi] * fex2(N1 - Mhi)
                      + ps[256 + rhi] * fex2(N2 - Mhi) + ps[384 + rhi] * fex2(N3 - Mhi);
            float flo = fex2(fscale[mt][0] - Mlo) / Zlo;
            float fhi = fex2(fscale[mt][1] - Mhi) / Zhi;
#pragma unroll
            for (int nt = 0; nt < 4; nt++) {
                int c = n02 + nt * 8 + t * 2;
                *reinterpret_cast<uint32_t*>(smem + SP_B + rlo * LDPB + c * 2) =
                    pack2(acc2[mt][nt][0] * flo, acc2[mt][nt][1] * flo);
                *reinterpret_cast<uint32_t*>(smem + SP_B + rhi * LDPB + c * 2) =
                    pack2(acc2[mt][nt][2] * fhi, acc2[mt][nt][3] * fhi);
            }
        }
    }
    __syncthreads();

    // =============== Phase 2c: O = P @ V  (causal kt-skip) ===============
    const int n03 = wn * 16;
    float acc3[2][2][4];
#pragma unroll
    for (int i = 0; i < 2; i++)
#pragma unroll
        for (int j = 0; j < 2; j++)
#pragma unroll
            for (int r = 0; r < 4; r++) acc3[i][j][r] = 0.f;

    const uint32_t prow = sbase + SP_B + (m0 + (lane & 15)) * LDPB + (lane >> 4) * 16;
    const uint32_t vbase = sbase + SV_B
                         + (((lane >> 3) & 1) * 8 + (lane & 7)) * LDA
                         + (lane >> 4) * 16 + n03 * 2;
    const int ktend = 2 * wm + 2;     // P cols beyond m0+31 are exactly zero
#pragma unroll 2
    for (int kt = 0; kt < ktend; kt++) {
        uint32_t a3[2][4], bv[4];
#pragma unroll
        for (int mt = 0; mt < 2; mt++) LDSM_X4(a3[mt], prow + mt * 16 * LDPB + kt * 32);
        LDSM_X4T(bv, vbase + kt * 16 * LDA);
#pragma unroll
        for (int mt = 0; mt < 2; mt++) {
            MMA16816(acc3[mt][0], a3[mt], bv[0], bv[1]);
            MMA16816(acc3[mt][1], a3[mt], bv[2], bv[3]);
        }
    }

    // output: fp32 float2 stores
    float* ob = out + b * (size_t)(T_SEQ * H_DIM);
#pragma unroll
    for (int mt = 0; mt < 2; mt++) {
        int rlo = m0 + mt * 16 + g, rhi = rlo + 8;
#pragma unroll
        for (int nt = 0; nt < 2; nt++) {
            int c = n03 + nt * 8 + t * 2;
            *reinterpret_cast<float2*>(ob + rlo * H_DIM + c) =
                make_float2(acc3[mt][nt][0], acc3[mt][nt][1]);
            *reinterpret_cast<float2*>(ob + rhi * H_DIM + c) =
                make_float2(acc3[mt][nt][2], acc3[mt][nt][3]);
        }
    }
}

extern "C" void kernel_launch(void* const* d_in, const int* in_sizes, int n_in,
                              void* d_out, int out_size) {
    const float* x  = (const float*)d_in[0];
    const float* Wq = (const float*)d_in[1];
    const float* Wk = (const float*)d_in[2];
    const float* Wv = (const float*)d_in[3];
    float* out = (float*)d_out;

    int B = in_sizes[0] / (T_SEQ * E_DIM);   // 4096

    cudaFuncSetAttribute(attn_fp16_kernel,
                         cudaFuncAttributeMaxDynamicSharedMemorySize,
                         (int)SMEM_BYTES);

    prep_w_kernel<<<12, 256>>>(Wq, Wk, Wv);
    attn_fp16_kernel<<<B, 512, SMEM_BYTES>>>(x, out);
}